// round 1
// baseline (speedup 1.0000x reference)
#include <cuda_runtime.h>
#include <math.h>

#define CB 16
#define CN 512
#define CD 256
#define CH 8
#define CDH 32
#define CDFF 1024
#define CL 2
#define NEG_INF_F (-1e9f)

// ---------------- scratch (static device allocations: allowed) ----------------
static __device__ float g_x [CB*CN*CD];
static __device__ float g_h [CB*CN*CD];
static __device__ float g_q [CB*CN*CD];
static __device__ float g_k [CB*CN*CD];
static __device__ float g_v [CB*CN*CD];
static __device__ float g_o [CB*CN*CD];
static __device__ float g_t [CB*CN*CD];
static __device__ float g_ff[CB*CN*CDFF];
static __device__ float g_alpha[CB*CN*CN];
static __device__ float g_e1[CB*CN];
static __device__ float g_e2[CB*CN];

// ---------------- generic strided-batched GEMM ----------------
// C = act( scale * A@B(^T) + bias ), 64x64 tile, BK=16, 256 threads, 4x4 per thread.
// Per-batch offsets: off = (z/div)*s1 + (z%div)*s2   (div>=1)
__global__ void gemm_kernel(const float* __restrict__ A, const float* __restrict__ B,
                            const float* __restrict__ bias, float* __restrict__ C,
                            int M, int Nc, int K, int lda, int ldb, int ldc,
                            long sA1, long sA2, int divA,
                            long sB1, long sB2, int divB,
                            long sC1, long sC2, int divC,
                            float scale, int act, int transB)
{
    const int bz = blockIdx.z;
    A += (long)(bz / divA) * sA1 + (long)(bz % divA) * sA2;
    B += (long)(bz / divB) * sB1 + (long)(bz % divB) * sB2;
    C += (long)(bz / divC) * sC1 + (long)(bz % divC) * sC2;

    __shared__ float As[16][64];   // [k][m]
    __shared__ float Bs[16][64];   // [k][n]

    const int tid = threadIdx.x;
    const int tx = tid & 15;       // 0..15  -> n-quad
    const int ty = tid >> 4;       // 0..15  -> m-quad
    const int row0 = blockIdx.y * 64;
    const int col0 = blockIdx.x * 64;

    float acc[4][4];
#pragma unroll
    for (int i = 0; i < 4; i++)
#pragma unroll
        for (int j = 0; j < 4; j++) acc[i][j] = 0.f;

    for (int k0 = 0; k0 < K; k0 += 16) {
        // load A tile (As[k][m]) - coalesced over k
        {
            const int k = tid & 15;
            const int gk = k0 + k;
#pragma unroll
            for (int p = 0; p < 4; p++) {
                const int m = (tid >> 4) + p * 16;
                const int gm = row0 + m;
                As[k][m] = (gm < M && gk < K) ? A[(long)gm * lda + gk] : 0.f;
            }
        }
        // load B tile (Bs[k][n])
        if (!transB) {
            const int n = tid & 63;
            const int gn = col0 + n;
#pragma unroll
            for (int p = 0; p < 4; p++) {
                const int k = (tid >> 6) + p * 4;
                const int gk = k0 + k;
                Bs[k][n] = (gk < K && gn < Nc) ? B[(long)gk * ldb + gn] : 0.f;
            }
        } else {
            const int k = tid & 15;
            const int gk = k0 + k;
#pragma unroll
            for (int p = 0; p < 4; p++) {
                const int n = (tid >> 4) + p * 16;
                const int gn = col0 + n;
                Bs[k][n] = (gn < Nc && gk < K) ? B[(long)gn * ldb + gk] : 0.f;
            }
        }
        __syncthreads();

#pragma unroll
        for (int kk = 0; kk < 16; kk++) {
            float4 a4 = *reinterpret_cast<const float4*>(&As[kk][ty * 4]);
            float4 b4 = *reinterpret_cast<const float4*>(&Bs[kk][tx * 4]);
            const float a[4] = {a4.x, a4.y, a4.z, a4.w};
            const float b[4] = {b4.x, b4.y, b4.z, b4.w};
#pragma unroll
            for (int i = 0; i < 4; i++)
#pragma unroll
                for (int j = 0; j < 4; j++) acc[i][j] = fmaf(a[i], b[j], acc[i][j]);
        }
        __syncthreads();
    }

#pragma unroll
    for (int i = 0; i < 4; i++) {
        const int gm = row0 + ty * 4 + i;
        if (gm >= M) continue;
#pragma unroll
        for (int j = 0; j < 4; j++) {
            const int gn = col0 + tx * 4 + j;
            if (gn >= Nc) continue;
            float vv = acc[i][j] * scale;
            if (bias) vv += bias[gn];
            if (act == 1) vv = fmaxf(vv, 0.f);
            else if (act == 2) vv = (vv > 0.f) ? vv : expm1f(vv);
            C[(long)gm * ldc + gn] = vv;
        }
    }
}

static inline void run_gemm(const float* A, const float* B, const float* bias, float* C,
                            int M, int Nc, int K, int lda, int ldb, int ldc,
                            int batch,
                            long sA1, long sA2, int divA,
                            long sB1, long sB2, int divB,
                            long sC1, long sC2, int divC,
                            float scale, int act, int transB)
{
    dim3 g((Nc + 63) / 64, (M + 63) / 64, batch);
    gemm_kernel<<<g, 256>>>(A, B, bias, C, M, Nc, K, lda, ldb, ldc,
                            sA1, sA2, divA, sB1, sB2, divB, sC1, sC2, divC,
                            scale, act, transB);
}

// ---------------- small fused kernels ----------------

__global__ void embed_kernel(const int* __restrict__ node, const float* __restrict__ embed,
                             float* __restrict__ x)
{
    const int row = blockIdx.x;          // B*N
    const int d = threadIdx.x;           // 256
    const int idx = node[row];
    x[(long)row * CD + d] = embed[(long)idx * CD + d];
}

// e1 = h@a1, e2 = h@a2 per row
__global__ void e12_kernel(const float* __restrict__ h, const float* __restrict__ a1,
                           const float* __restrict__ a2, float* __restrict__ e1,
                           float* __restrict__ e2)
{
    const int row = blockIdx.x;
    const int d = threadIdx.x;
    __shared__ float s1[256], s2[256];
    const float hv = h[(long)row * CD + d];
    s1[d] = hv * a1[d];
    s2[d] = hv * a2[d];
    __syncthreads();
    for (int off = 128; off > 0; off >>= 1) {
        if (d < off) { s1[d] += s1[d + off]; s2[d] += s2[d + off]; }
        __syncthreads();
    }
    if (d == 0) { e1[row] = s1[0]; e2[row] = s2[0]; }
}

// alpha[b,i,:] = softmax_j( mask(adj, leakyrelu(e1_i + e2_j)) )
__global__ void gat_softmax_kernel(const float* __restrict__ e1, const float* __restrict__ e2,
                                   const int* __restrict__ edge, float* __restrict__ alpha)
{
    const int row = blockIdx.x;          // b*N + i
    const int b = row / CN;
    const int t = threadIdx.x;           // 256, handles 2 j each
    __shared__ float red[256];
    const float ei = e1[row];

    float vals[2];
#pragma unroll
    for (int p = 0; p < 2; p++) {
        const int j = t + p * 256;
        float e = ei + e2[b * CN + j];
        e = (e >= 0.f) ? e : 0.2f * e;
        const bool adj = edge[(long)row * CN + j] > 0;
        vals[p] = adj ? e : NEG_INF_F;
    }
    // max
    red[t] = fmaxf(vals[0], vals[1]);
    __syncthreads();
    for (int off = 128; off > 0; off >>= 1) {
        if (t < off) red[t] = fmaxf(red[t], red[t + off]);
        __syncthreads();
    }
    const float m = red[0];
    __syncthreads();
    float ex[2];
    ex[0] = __expf(vals[0] - m);
    ex[1] = __expf(vals[1] - m);
    red[t] = ex[0] + ex[1];
    __syncthreads();
    for (int off = 128; off > 0; off >>= 1) {
        if (t < off) red[t] += red[t + off];
        __syncthreads();
    }
    const float inv = 1.f / red[0];
#pragma unroll
    for (int p = 0; p < 2; p++) {
        const int j = t + p * 256;
        alpha[(long)row * CN + j] = ex[p] * inv;
    }
}

// softmax over last dim of scores [B,H,N,N] in place, with +mask*NEG_INF
__global__ void mha_softmax_kernel(float* __restrict__ s, const int* __restrict__ mask)
{
    const int r = blockIdx.x;            // b*H*N + h*N + i
    const int b = r / (CH * CN);
    const int t = threadIdx.x;           // 256, 2 j each
    __shared__ float red[256];
    float* srow = s + (long)r * CN;

    float vals[2];
#pragma unroll
    for (int p = 0; p < 2; p++) {
        const int j = t + p * 256;
        vals[p] = srow[j] + (float)mask[b * CN + j] * NEG_INF_F;
    }
    red[t] = fmaxf(vals[0], vals[1]);
    __syncthreads();
    for (int off = 128; off > 0; off >>= 1) {
        if (t < off) red[t] = fmaxf(red[t], red[t + off]);
        __syncthreads();
    }
    const float m = red[0];
    __syncthreads();
    float ex[2];
    ex[0] = __expf(vals[0] - m);
    ex[1] = __expf(vals[1] - m);
    red[t] = ex[0] + ex[1];
    __syncthreads();
    for (int off = 128; off > 0; off >>= 1) {
        if (t < off) red[t] += red[t + off];
        __syncthreads();
    }
    const float inv = 1.f / red[0];
#pragma unroll
    for (int p = 0; p < 2; p++) {
        const int j = t + p * 256;
        srow[j] = ex[p] * inv;
    }
}

// x = x*sqrt(D) + PE(n,d)
__global__ void scale_pe_kernel(float* __restrict__ x)
{
    const int row = blockIdx.x;          // b*N + n
    const int n = row % CN;
    const int d = threadIdx.x;
    const float expo = (2.0f * (float)(d >> 1)) / (float)CD;
    const float angle = (float)n * powf(10000.0f, -expo);
    const float pe = (d & 1) ? cosf(angle) : sinf(angle);
    const long idx = (long)row * CD + d;
    x[idx] = x[idx] * 16.0f + pe;       // sqrt(256) = 16
}

// out = LN(x + delta) * g + b  (row = B*N, D=256, one thread per element)
__global__ void ln_kernel(const float* __restrict__ x, const float* __restrict__ delta,
                          const float* __restrict__ g, const float* __restrict__ bb,
                          float* __restrict__ out)
{
    const int row = blockIdx.x;
    const int d = threadIdx.x;
    __shared__ float red[256];
    const long idx = (long)row * CD + d;
    const float v = x[idx] + delta[idx];
    red[d] = v;
    __syncthreads();
    for (int off = 128; off > 0; off >>= 1) {
        if (d < off) red[d] += red[d + off];
        __syncthreads();
    }
    const float mu = red[0] * (1.0f / CD);
    __syncthreads();
    const float c = v - mu;
    red[d] = c * c;
    __syncthreads();
    for (int off = 128; off > 0; off >>= 1) {
        if (d < off) red[d] += red[d + off];
        __syncthreads();
    }
    const float var = red[0] * (1.0f / CD);
    out[idx] = c * rsqrtf(var + 1e-6f) * g[d] + bb[d];
}

__global__ void copy_kernel(const float* __restrict__ src, float* __restrict__ dst, long n)
{
    const long i = (long)blockIdx.x * blockDim.x + threadIdx.x;
    if (i < n) dst[i] = src[i];
}

// ---------------- launch ----------------
extern "C" void kernel_launch(void* const* d_in, const int* in_sizes, int n_in,
                              void* d_out, int out_size)
{
    const int*   node  = (const int*)  d_in[0];
    const int*   edge  = (const int*)  d_in[1];
    const int*   mask  = (const int*)  d_in[2];
    const float* embed = (const float*)d_in[4];
    const float* Wg    = (const float*)d_in[5];
    const float* a1    = (const float*)d_in[6];
    const float* a2    = (const float*)d_in[7];
    const float* Wq    = (const float*)d_in[8];
    const float* bq    = (const float*)d_in[9];
    const float* Wk    = (const float*)d_in[10];
    const float* bk    = (const float*)d_in[11];
    const float* Wv    = (const float*)d_in[12];
    const float* bv    = (const float*)d_in[13];
    const float* Wo    = (const float*)d_in[14];
    const float* bo    = (const float*)d_in[15];
    const float* W1    = (const float*)d_in[16];
    const float* b1    = (const float*)d_in[17];
    const float* W2    = (const float*)d_in[18];
    const float* b2    = (const float*)d_in[19];
    const float* ln1g  = (const float*)d_in[20];
    const float* ln1b  = (const float*)d_in[21];
    const float* ln2g  = (const float*)d_in[22];
    const float* ln2b  = (const float*)d_in[23];

    float *x, *h, *q, *k, *v, *o, *t, *ff, *alpha, *e1, *e2;
    cudaGetSymbolAddress((void**)&x,  g_x);
    cudaGetSymbolAddress((void**)&h,  g_h);
    cudaGetSymbolAddress((void**)&q,  g_q);
    cudaGetSymbolAddress((void**)&k,  g_k);
    cudaGetSymbolAddress((void**)&v,  g_v);
    cudaGetSymbolAddress((void**)&o,  g_o);
    cudaGetSymbolAddress((void**)&t,  g_t);
    cudaGetSymbolAddress((void**)&ff, g_ff);
    cudaGetSymbolAddress((void**)&alpha, g_alpha);
    cudaGetSymbolAddress((void**)&e1, g_e1);
    cudaGetSymbolAddress((void**)&e2, g_e2);

    float* out_x    = (float*)d_out;                       // [B,N,D]
    float* out_attn = (float*)d_out + (long)CB * CN * CD;  // [B,H,N,N]

    const int M  = CB * CN;          // 8192
    const long ND = (long)CN * CD;   // per-batch x stride
    const long NN = (long)CN * CN;

    // ---- embedding ----
    embed_kernel<<<M, CD>>>(node, embed, x);

    // ---- GAT hops ----
    for (int hop = 0; hop < 2; hop++) {
        run_gemm(x, Wg, nullptr, h, M, CD, CD, CD, CD, CD,
                 1, 0, 0, 1, 0, 0, 1, 0, 0, 1, 1.0f, 0, 0);
        e12_kernel<<<M, CD>>>(h, a1, a2, e1, e2);
        gat_softmax_kernel<<<M, 256>>>(e1, e2, edge, alpha);
        // x = elu(alpha @ h), batched over B
        run_gemm(alpha, h, nullptr, x, CN, CD, CN, CN, CD, CD,
                 CB, NN, 0, 1, ND, 0, 1, ND, 0, 1, 1.0f, 2, 0);
    }

    // ---- scale + positional encoding ----
    scale_pe_kernel<<<M, CD>>>(x);

    // ---- transformer layers ----
    const float inv_sqrt_dh = 0.17677669529663687f; // 1/sqrt(32)
    for (int l = 0; l < CL; l++) {
        const long wOff = (long)l * CD * CD;
        run_gemm(x, Wq + wOff, bq + l * CD, q, M, CD, CD, CD, CD, CD,
                 1, 0, 0, 1, 0, 0, 1, 0, 0, 1, 1.0f, 0, 0);
        run_gemm(x, Wk + wOff, bk + l * CD, k, M, CD, CD, CD, CD, CD,
                 1, 0, 0, 1, 0, 0, 1, 0, 0, 1, 1.0f, 0, 0);
        run_gemm(x, Wv + wOff, bv + l * CD, v, M, CD, CD, CD, CD, CD,
                 1, 0, 0, 1, 0, 0, 1, 0, 0, 1, 1.0f, 0, 0);

        // scores = q @ k^T / sqrt(dh)   batched over B*H, written into d_out attn region
        run_gemm(q, k, nullptr, out_attn, CN, CN, CDH, CD, CD, CN,
                 CB * CH, ND, CDH, CH,   // A: z/H -> batch, z%H -> head col offset
                 ND, CDH, CH,
                 NN, 0, 1,
                 inv_sqrt_dh, 0, 1);

        mha_softmax_kernel<<<CB * CH * CN, 256>>>(out_attn, mask);

        // o = attn @ v   (per head, Nc = 32)
        run_gemm(out_attn, v, nullptr, o, CN, CDH, CN, CN, CD, CD,
                 CB * CH, NN, 0, 1,
                 ND, CDH, CH,
                 ND, CDH, CH,
                 1.0f, 0, 0);

        // t = o @ Wo + bo ; x = LN(x + t)
        run_gemm(o, Wo + wOff, bo + l * CD, t, M, CD, CD, CD, CD, CD,
                 1, 0, 0, 1, 0, 0, 1, 0, 0, 1, 1.0f, 0, 0);
        ln_kernel<<<M, CD>>>(x, t, ln1g + l * CD, ln1b + l * CD, x);

        // FFN
        run_gemm(x, W1 + (long)l * CD * CDFF, b1 + l * CDFF, ff, M, CDFF, CD,
                 CD, CDFF, CDFF, 1, 0, 0, 1, 0, 0, 1, 0, 0, 1, 1.0f, 1, 0);
        run_gemm(ff, W2 + (long)l * CDFF * CD, b2 + l * CD, t, M, CD, CDFF,
                 CDFF, CD, CD, 1, 0, 0, 1, 0, 0, 1, 0, 0, 1, 1.0f, 0, 0);
        ln_kernel<<<M, CD>>>(x, t, ln2g + l * CD, ln2b + l * CD, x);
    }

    // ---- write x output ----
    const long xcount = (long)CB * CN * CD;
    copy_kernel<<<(int)((xcount + 255) / 256), 256>>>(x, out_x, xcount);
}